// round 3
// baseline (speedup 1.0000x reference)
#include <cuda_runtime.h>
#include <cuda_bf16.h>
#include <math_constants.h>
#include <cstdint>

#define N_NODES 50000
#define N_EDGES 800000
#define HID 128
#define PW 384   // fused precompute width: [0:128)=z@Ws, [128:256)=z@Wd, [256:384)=z@W1a

// ---------------- scratch ----------------
__device__ float g_P[(size_t)N_NODES * PW];
__device__ float g_agg[(size_t)N_NODES * HID];
__device__ float g_hidden[(size_t)N_NODES * HID];
__device__ int   g_count[N_NODES];
__device__ int   g_offset[N_NODES];
__device__ int   g_cursor[N_NODES];
__device__ int   g_sorted_src[N_EDGES];
__device__ float g_sorted_w[N_EDGES];

// ---------------- mma.sync helpers (portable sm_80+ PTX, no 'a' features) ----------------
__device__ __forceinline__ uint32_t smem_u32(const void* p) {
    uint32_t a;
    asm("{ .reg .u64 t; cvta.to.shared.u64 t, %1; cvt.u32.u64 %0, t; }" : "=r"(a) : "l"(p));
    return a;
}
__device__ __forceinline__ void ldsm_x4(uint32_t* r, uint32_t addr) {
    asm volatile("ldmatrix.sync.aligned.m8n8.x4.shared.b16 {%0,%1,%2,%3}, [%4];"
                 : "=r"(r[0]), "=r"(r[1]), "=r"(r[2]), "=r"(r[3]) : "r"(addr));
}
__device__ __forceinline__ void ldsm_x4_t(uint32_t* r, uint32_t addr) {
    asm volatile("ldmatrix.sync.aligned.m8n8.x4.trans.shared.b16 {%0,%1,%2,%3}, [%4];"
                 : "=r"(r[0]), "=r"(r[1]), "=r"(r[2]), "=r"(r[3]) : "r"(addr));
}
__device__ __forceinline__ void mma16816(float* c, const uint32_t* a, const uint32_t* b) {
    asm volatile(
        "mma.sync.aligned.m16n8k16.row.col.f32.bf16.bf16.f32 "
        "{%0,%1,%2,%3}, {%4,%5,%6,%7}, {%8,%9}, {%0,%1,%2,%3};"
        : "+f"(c[0]), "+f"(c[1]), "+f"(c[2]), "+f"(c[3])
        : "r"(a[0]), "r"(a[1]), "r"(a[2]), "r"(a[3]), "r"(b[0]), "r"(b[1]));
}
__device__ __forceinline__ uint32_t pack2(float x, float y) {
    __nv_bfloat162 h = __floats2bfloat162_rn(x, y);
    return *(uint32_t*)&h;
}

// swizzled byte offset inside a [128 rows][128 cols] bf16 tile (256B rows).
// 16B chunk index XOR (row & 7) -> conflict-free ldmatrix + conflict-free STS.
__device__ __forceinline__ uint32_t swz(int row, int col) {
    return (uint32_t)(row * 256 + ((((col >> 3) ^ (row & 7))) << 4) + (col & 7) * 2);
}

// smem plan (dynamic, 128 KB)
#define SM_AHI 0
#define SM_ALO 32768
#define SM_BHI 65536
#define SM_BLO 98304
#define SM_TOTAL 131072

// out[r][ocol0 + c] = f(A_tile @ B + bias + Cadd)
// A: [M,128] fp32 row-major.  B: [128,128] fp32 row-major (K-major weights).
// Split: D = Ahi@Bhi + Ahi@Blo + Alo@Bhi (fp32 accum).
__global__ __launch_bounds__(256)
void mma_gemm(const float* __restrict__ A,
              const float* __restrict__ Bp0, const float* __restrict__ Bp1,
              const float* __restrict__ Bp2,
              const float* __restrict__ bias, const float* __restrict__ Cadd, int ldCadd,
              float* __restrict__ out, int ldOut, int M, int relu)
{
    extern __shared__ char smem[];
    const uint32_t sb = smem_u32(smem);
    const int tid = threadIdx.x;
    const int wid = tid >> 5;
    const int lane = tid & 31;
    const int bm0 = blockIdx.x * 128;
    const int by = blockIdx.y;
    const float* B = (by == 0) ? Bp0 : ((by == 1) ? Bp1 : Bp2);
    const int ocol0 = by * 128;

    // ---- convert A tile: fp32 -> (hi, lo) bf16, swizzled smem ----
#pragma unroll
    for (int i = 0; i < 32; i++) {
        int p = tid + i * 256;              // pair index 0..8191
        int row = p >> 6;
        int col = (p & 63) * 2;
        float2 v = make_float2(0.f, 0.f);
        int gr = bm0 + row;
        if (gr < M) v = *(const float2*)(A + (size_t)gr * 128 + col);
        float hx = __bfloat162float(__float2bfloat16(v.x));
        float hy = __bfloat162float(__float2bfloat16(v.y));
        uint32_t off = swz(row, col);
        *(uint32_t*)(smem + SM_AHI + off) = pack2(hx, hy);
        *(uint32_t*)(smem + SM_ALO + off) = pack2(v.x - hx, v.y - hy);
    }
    // ---- convert B tile (direct K-major copy) ----
#pragma unroll
    for (int i = 0; i < 32; i++) {
        int p = tid + i * 256;
        int row = p >> 6;                   // k
        int col = (p & 63) * 2;             // n
        float2 v = *(const float2*)(B + (size_t)row * 128 + col);
        float hx = __bfloat162float(__float2bfloat16(v.x));
        float hy = __bfloat162float(__float2bfloat16(v.y));
        uint32_t off = swz(row, col);
        *(uint32_t*)(smem + SM_BHI + off) = pack2(hx, hy);
        *(uint32_t*)(smem + SM_BLO + off) = pack2(v.x - hx, v.y - hy);
    }
    __syncthreads();

    // ---- warp tiling: warp (wm, wn) -> rows wm*64..+63, cols wn*32..+31 ----
    const int wm = wid & 1;
    const int wn = wid >> 1;
    const int sub = lane >> 3;        // ldmatrix sub-matrix id
    const int l7 = lane & 7;
    const int radd = (sub & 1) * 8;   // row add within 16x16
    const int cadd = (sub >> 1) * 8;  // col add within 16x16

    float acc[4][4][4];
#pragma unroll
    for (int mt = 0; mt < 4; mt++)
#pragma unroll
        for (int nt = 0; nt < 4; nt++)
#pragma unroll
            for (int j = 0; j < 4; j++) acc[mt][nt][j] = 0.f;

#pragma unroll
    for (int ks = 0; ks < 8; ks++) {
        const int k0 = ks * 16;
        uint32_t aH[4][4], aL[4][4], bH[2][4], bL[2][4];
#pragma unroll
        for (int mt = 0; mt < 4; mt++) {
            int ar = wm * 64 + mt * 16 + l7 + radd;
            int ac = k0 + cadd;
            uint32_t o = swz(ar, ac);
            ldsm_x4(aH[mt], sb + SM_AHI + o);
            ldsm_x4(aL[mt], sb + SM_ALO + o);
        }
#pragma unroll
        for (int pr = 0; pr < 2; pr++) {
            int kr = k0 + l7 + radd;
            int nc = wn * 32 + pr * 16 + cadd;
            uint32_t o = swz(kr, nc);
            ldsm_x4_t(bH[pr], sb + SM_BHI + o);
            ldsm_x4_t(bL[pr], sb + SM_BLO + o);
        }
#pragma unroll
        for (int mt = 0; mt < 4; mt++)
#pragma unroll
            for (int nt = 0; nt < 4; nt++) {
                const uint32_t* bh = &bH[nt >> 1][(nt & 1) * 2];
                const uint32_t* bl = &bL[nt >> 1][(nt & 1) * 2];
                mma16816(acc[mt][nt], aH[mt], bh);   // hi*hi
                mma16816(acc[mt][nt], aH[mt], bl);   // hi*lo
                mma16816(acc[mt][nt], aL[mt], bh);   // lo*hi
            }
    }

    // ---- epilogue ----
    const int g = lane >> 2;
    const int tg = lane & 3;
#pragma unroll
    for (int mt = 0; mt < 4; mt++) {
#pragma unroll
        for (int half = 0; half < 2; half++) {
            int r = bm0 + wm * 64 + mt * 16 + g + half * 8;
            if (r >= M) continue;
            float* orow = out + (size_t)r * ldOut + ocol0;
            const float* crow = Cadd ? (Cadd + (size_t)r * ldCadd) : nullptr;
#pragma unroll
            for (int nt = 0; nt < 4; nt++) {
                int lc = wn * 32 + nt * 8 + 2 * tg;
                float2 v;
                v.x = acc[mt][nt][half * 2 + 0];
                v.y = acc[mt][nt][half * 2 + 1];
                if (bias) { v.x += bias[lc]; v.y += bias[lc + 1]; }
                if (crow) { v.x += crow[lc]; v.y += crow[lc + 1]; }
                if (relu) { v.x = fmaxf(v.x, 0.f); v.y = fmaxf(v.y, 0.f); }
                *(float2*)(orow + lc) = v;
            }
        }
    }
}

// ---------------- edge counting sort + aggregation ----------------
__global__ void zero_count_kernel() {
    int i = blockIdx.x * blockDim.x + threadIdx.x;
    if (i < N_NODES) g_count[i] = 0;
}

__global__ void hist_kernel(const int* __restrict__ edst) {
    int i = blockIdx.x * blockDim.x + threadIdx.x;
    if (i < N_EDGES) atomicAdd(&g_count[edst[i]], 1);
}

__global__ void scan_kernel() {
    const int T = 1024;
    const int C = (N_NODES + T - 1) / T;
    int t = threadIdx.x;
    int s = t * C;
    int e = min(s + C, N_NODES);
    int sum = 0;
    for (int i = s; i < e; i++) sum += g_count[i];

    int lane = t & 31, warp = t >> 5;
    int incl = sum;
#pragma unroll
    for (int o = 1; o < 32; o <<= 1) {
        int v = __shfl_up_sync(0xffffffffu, incl, o);
        if (lane >= o) incl += v;
    }
    __shared__ int wsum[32];
    if (lane == 31) wsum[warp] = incl;
    __syncthreads();
    if (warp == 0) {
        int v = wsum[lane];
        int wi = v;
#pragma unroll
        for (int o = 1; o < 32; o <<= 1) {
            int u = __shfl_up_sync(0xffffffffu, wi, o);
            if (lane >= o) wi += u;
        }
        wsum[lane] = wi - v;
    }
    __syncthreads();
    int run = wsum[warp] + (incl - sum);
    for (int i = s; i < e; i++) {
        g_offset[i] = run;
        g_cursor[i] = run;
        run += g_count[i];
    }
}

__global__ void scatter_kernel(const int* __restrict__ esrc, const int* __restrict__ edst,
                               const float* __restrict__ ew) {
    int i = blockIdx.x * blockDim.x + threadIdx.x;
    if (i >= N_EDGES) return;
    int d = edst[i];
    int pos = atomicAdd(&g_cursor[d], 1);
    g_sorted_src[pos] = esrc[i];
    g_sorted_w[pos] = ew[i];
}

__global__ void agg_kernel(const float* __restrict__ Wm, const float* __restrict__ bm) {
    int gw = (blockIdx.x * blockDim.x + threadIdx.x) >> 5;
    int lane = threadIdx.x & 31;
    if (gw >= N_NODES) return;

    int start = g_offset[gw];
    int cnt = g_count[gw];
    float4 outv = make_float4(0.f, 0.f, 0.f, 0.f);
    if (cnt > 0) {
        float4 w4 = *(const float4*)(Wm + 256 * 128 + lane * 4);
        float4 m = make_float4(-CUDART_INF_F, -CUDART_INF_F, -CUDART_INF_F, -CUDART_INF_F);
        int e = start, end = start + cnt;
        for (; e < end; e++) {
            int s = g_sorted_src[e];
            float w = g_sorted_w[e];
            float4 p = *(const float4*)(g_P + (size_t)s * PW + lane * 4);
            m.x = fmaxf(m.x, fmaf(w, w4.x, p.x));
            m.y = fmaxf(m.y, fmaf(w, w4.y, p.y));
            m.z = fmaxf(m.z, fmaf(w, w4.z, p.z));
            m.w = fmaxf(m.w, fmaf(w, w4.w, p.w));
        }
        float4 q = *(const float4*)(g_P + (size_t)gw * PW + 128 + lane * 4);
        float4 b = *(const float4*)(bm + lane * 4);
        outv.x = q.x + b.x + m.x;
        outv.y = q.y + b.y + m.y;
        outv.z = q.z + b.z + m.z;
        outv.w = q.w + b.w + m.w;
    }
    *(float4*)(g_agg + (size_t)gw * HID + lane * 4) = outv;
}

// ---------------- launch ----------------
extern "C" void kernel_launch(void* const* d_in, const int* in_sizes, int n_in,
                              void* d_out, int out_size) {
    const float* z    = (const float*)d_in[0];
    const float* ew   = (const float*)d_in[1];
    const int*   esrc = (const int*)d_in[2];
    const int*   edst = (const int*)d_in[3];
    const float* Wm   = (const float*)d_in[4];
    const float* bm   = (const float*)d_in[5];
    const float* W1   = (const float*)d_in[6];
    const float* b1   = (const float*)d_in[7];
    const float* W2   = (const float*)d_in[8];
    const float* b2   = (const float*)d_in[9];
    float* out = (float*)d_out;

    float *P, *AGG, *HIDN;
    cudaGetSymbolAddress((void**)&P, g_P);
    cudaGetSymbolAddress((void**)&AGG, g_agg);
    cudaGetSymbolAddress((void**)&HIDN, g_hidden);

    static bool attr_set = false;
    if (!attr_set) {
        cudaFuncSetAttribute(mma_gemm, cudaFuncAttributeMaxDynamicSharedMemorySize, SM_TOTAL);
        attr_set = true;
    }

    const int NT = (N_NODES + 127) / 128;  // 391 row tiles

    zero_count_kernel<<<(N_NODES + 255) / 256, 256>>>();

    // P[:,0:128)=z@Ws, [128:256)=z@Wd, [256:384)=z@W1a  (fused via grid.y)
    mma_gemm<<<dim3(NT, 3), 256, SM_TOTAL>>>(
        z, Wm + 128 * 128, Wm, W1, nullptr, nullptr, 0, P, PW, N_NODES, 0);

    hist_kernel<<<N_EDGES / 256, 256>>>(edst);
    scan_kernel<<<1, 1024>>>();
    scatter_kernel<<<N_EDGES / 256, 256>>>(esrc, edst, ew);
    agg_kernel<<<(N_NODES * 32) / 256, 256>>>(Wm, bm);

    // hidden = relu(agg @ W1b + b1 + P[:,256:384))
    mma_gemm<<<dim3(NT, 1), 256, SM_TOTAL>>>(
        AGG, W1 + 128 * 128, nullptr, nullptr, b1, P + 256, PW, HIDN, HID, N_NODES, 1);

    // out = hidden @ W2 + b2
    mma_gemm<<<dim3(NT, 1), 256, SM_TOTAL>>>(
        HIDN, W2, nullptr, nullptr, b2, nullptr, 0, out, HID, N_NODES, 0);
}

// round 4
// speedup vs baseline: 1.9453x; 1.9453x over previous
#include <cuda_runtime.h>
#include <cuda_bf16.h>
#include <math_constants.h>
#include <cstdint>

#define N_NODES 50000
#define N_EDGES 800000
#define HID 128
#define PW 384   // fused precompute width: [0:128)=z@Ws, [128:256)=z@Wd, [256:384)=z@W1a
#define SCAN_BLOCKS ((N_NODES + 255) / 256)   // 196

// ---------------- scratch ----------------
__device__ float g_P[(size_t)N_NODES * PW];
__device__ float g_agg[(size_t)N_NODES * HID];
__device__ float g_hidden[(size_t)N_NODES * HID];
__device__ int   g_count[N_NODES];
__device__ int   g_offset[N_NODES];
__device__ int   g_cursor[N_NODES];
__device__ int   g_blocksum[SCAN_BLOCKS];
__device__ int   g_sorted_src[N_EDGES];
__device__ float g_sorted_w[N_EDGES];

// ---------------- mma.sync helpers (portable sm_80+ PTX, no 'a' features) ----------------
__device__ __forceinline__ uint32_t smem_u32(const void* p) {
    uint32_t a;
    asm("{ .reg .u64 t; cvta.to.shared.u64 t, %1; cvt.u32.u64 %0, t; }" : "=r"(a) : "l"(p));
    return a;
}
__device__ __forceinline__ void ldsm_x4(uint32_t* r, uint32_t addr) {
    asm volatile("ldmatrix.sync.aligned.m8n8.x4.shared.b16 {%0,%1,%2,%3}, [%4];"
                 : "=r"(r[0]), "=r"(r[1]), "=r"(r[2]), "=r"(r[3]) : "r"(addr));
}
__device__ __forceinline__ void ldsm_x4_t(uint32_t* r, uint32_t addr) {
    asm volatile("ldmatrix.sync.aligned.m8n8.x4.trans.shared.b16 {%0,%1,%2,%3}, [%4];"
                 : "=r"(r[0]), "=r"(r[1]), "=r"(r[2]), "=r"(r[3]) : "r"(addr));
}
__device__ __forceinline__ void mma16816(float* c, const uint32_t* a, const uint32_t* b) {
    asm volatile(
        "mma.sync.aligned.m16n8k16.row.col.f32.bf16.bf16.f32 "
        "{%0,%1,%2,%3}, {%4,%5,%6,%7}, {%8,%9}, {%0,%1,%2,%3};"
        : "+f"(c[0]), "+f"(c[1]), "+f"(c[2]), "+f"(c[3])
        : "r"(a[0]), "r"(a[1]), "r"(a[2]), "r"(a[3]), "r"(b[0]), "r"(b[1]));
}
__device__ __forceinline__ uint32_t pack2(float x, float y) {
    __nv_bfloat162 h = __floats2bfloat162_rn(x, y);
    return *(uint32_t*)&h;
}

// swizzled byte offset inside a [128 rows][128 cols] bf16 tile (256B rows).
__device__ __forceinline__ uint32_t swz(int row, int col) {
    return (uint32_t)(row * 256 + ((((col >> 3) ^ (row & 7))) << 4) + (col & 7) * 2);
}

// smem plan (dynamic, 128 KB)
#define SM_AHI 0
#define SM_ALO 32768
#define SM_BHI 65536
#define SM_BLO 98304
#define SM_TOTAL 131072

// out[r][ocol0 + c] = f(A_tile @ B + bias + Cadd)
// Split: D = Ahi@Bhi + Ahi@Blo + Alo@Bhi (fp32 accum).
__global__ __launch_bounds__(256)
void mma_gemm(const float* __restrict__ A,
              const float* __restrict__ Bp0, const float* __restrict__ Bp1,
              const float* __restrict__ Bp2,
              const float* __restrict__ bias, const float* __restrict__ Cadd, int ldCadd,
              float* __restrict__ out, int ldOut, int M, int relu)
{
    extern __shared__ char smem[];
    const uint32_t sb = smem_u32(smem);
    const int tid = threadIdx.x;
    const int wid = tid >> 5;
    const int lane = tid & 31;
    const int bm0 = blockIdx.x * 128;
    const int by = blockIdx.y;
    const float* B = (by == 0) ? Bp0 : ((by == 1) ? Bp1 : Bp2);
    const int ocol0 = by * 128;

    // ---- convert A tile: fp32 -> (hi, lo) bf16, swizzled smem ----
#pragma unroll
    for (int i = 0; i < 32; i++) {
        int p = tid + i * 256;              // pair index 0..8191
        int row = p >> 6;
        int col = (p & 63) * 2;
        float2 v = make_float2(0.f, 0.f);
        int gr = bm0 + row;
        if (gr < M) v = *(const float2*)(A + (size_t)gr * 128 + col);
        float hx = __bfloat162float(__float2bfloat16(v.x));
        float hy = __bfloat162float(__float2bfloat16(v.y));
        uint32_t off = swz(row, col);
        *(uint32_t*)(smem + SM_AHI + off) = pack2(hx, hy);
        *(uint32_t*)(smem + SM_ALO + off) = pack2(v.x - hx, v.y - hy);
    }
    // ---- convert B tile (direct K-major copy) ----
#pragma unroll
    for (int i = 0; i < 32; i++) {
        int p = tid + i * 256;
        int row = p >> 6;                   // k
        int col = (p & 63) * 2;             // n
        float2 v = *(const float2*)(B + (size_t)row * 128 + col);
        float hx = __bfloat162float(__float2bfloat16(v.x));
        float hy = __bfloat162float(__float2bfloat16(v.y));
        uint32_t off = swz(row, col);
        *(uint32_t*)(smem + SM_BHI + off) = pack2(hx, hy);
        *(uint32_t*)(smem + SM_BLO + off) = pack2(v.x - hx, v.y - hy);
    }
    __syncthreads();

    // ---- warp tiling: warp (wm, wn) -> rows wm*64..+63, cols wn*32..+31 ----
    const int wm = wid & 1;
    const int wn = wid >> 1;
    const int sub = lane >> 3;
    const int l7 = lane & 7;
    const int radd = (sub & 1) * 8;
    const int cadd = (sub >> 1) * 8;

    float acc[4][4][4];
#pragma unroll
    for (int mt = 0; mt < 4; mt++)
#pragma unroll
        for (int nt = 0; nt < 4; nt++)
#pragma unroll
            for (int j = 0; j < 4; j++) acc[mt][nt][j] = 0.f;

#pragma unroll
    for (int ks = 0; ks < 8; ks++) {
        const int k0 = ks * 16;
        uint32_t aH[4][4], aL[4][4], bH[2][4], bL[2][4];
#pragma unroll
        for (int mt = 0; mt < 4; mt++) {
            int ar = wm * 64 + mt * 16 + l7 + radd;
            int ac = k0 + cadd;
            uint32_t o = swz(ar, ac);
            ldsm_x4(aH[mt], sb + SM_AHI + o);
            ldsm_x4(aL[mt], sb + SM_ALO + o);
        }
#pragma unroll
        for (int pr = 0; pr < 2; pr++) {
            int kr = k0 + l7 + radd;
            int nc = wn * 32 + pr * 16 + cadd;
            uint32_t o = swz(kr, nc);
            ldsm_x4_t(bH[pr], sb + SM_BHI + o);
            ldsm_x4_t(bL[pr], sb + SM_BLO + o);
        }
#pragma unroll
        for (int mt = 0; mt < 4; mt++)
#pragma unroll
            for (int nt = 0; nt < 4; nt++) {
                const uint32_t* bh = &bH[nt >> 1][(nt & 1) * 2];
                const uint32_t* bl = &bL[nt >> 1][(nt & 1) * 2];
                mma16816(acc[mt][nt], aH[mt], bh);   // hi*hi
                mma16816(acc[mt][nt], aH[mt], bl);   // hi*lo
                mma16816(acc[mt][nt], aL[mt], bh);   // lo*hi
            }
    }

    // ---- epilogue ----
    const int g = lane >> 2;
    const int tg = lane & 3;
#pragma unroll
    for (int mt = 0; mt < 4; mt++) {
#pragma unroll
        for (int half = 0; half < 2; half++) {
            int r = bm0 + wm * 64 + mt * 16 + g + half * 8;
            if (r >= M) continue;
            float* orow = out + (size_t)r * ldOut + ocol0;
            const float* crow = Cadd ? (Cadd + (size_t)r * ldCadd) : nullptr;
#pragma unroll
            for (int nt = 0; nt < 4; nt++) {
                int lc = wn * 32 + nt * 8 + 2 * tg;
                float2 v;
                v.x = acc[mt][nt][half * 2 + 0];
                v.y = acc[mt][nt][half * 2 + 1];
                if (bias) { v.x += bias[lc]; v.y += bias[lc + 1]; }
                if (crow) { v.x += crow[lc]; v.y += crow[lc + 1]; }
                if (relu) { v.x = fmaxf(v.x, 0.f); v.y = fmaxf(v.y, 0.f); }
                *(float2*)(orow + lc) = v;
            }
        }
    }
}

// ---------------- edge counting sort ----------------
__global__ void zero_count_kernel() {
    int i = blockIdx.x * blockDim.x + threadIdx.x;
    if (i < N_NODES) g_count[i] = 0;
}

__global__ void hist_kernel(const int* __restrict__ edst) {
    int i = blockIdx.x * blockDim.x + threadIdx.x;
    if (i < N_EDGES) atomicAdd(&g_count[edst[i]], 1);
}

// phase 1: block-local exclusive scan -> g_offset (local), block total -> g_blocksum
__global__ void scan_local() {
    int b = blockIdx.x, t = threadIdx.x;
    int i = b * 256 + t;
    int v = (i < N_NODES) ? g_count[i] : 0;
    int lane = t & 31, w = t >> 5;
    int incl = v;
#pragma unroll
    for (int o = 1; o < 32; o <<= 1) {
        int y = __shfl_up_sync(0xffffffffu, incl, o);
        if (lane >= o) incl += y;
    }
    __shared__ int ws[8];
    if (lane == 31) ws[w] = incl;
    __syncthreads();
    if (t < 8) {
        int x = ws[t];
#pragma unroll
        for (int o = 1; o < 8; o <<= 1) {
            int y = __shfl_up_sync(0xffu, x, o, 8);
            if (t >= o) x += y;
        }
        ws[t] = x;   // inclusive warp-sums
    }
    __syncthreads();
    int excl = incl - v + (w > 0 ? ws[w - 1] : 0);
    if (i < N_NODES) g_offset[i] = excl;
    if (t == 255) g_blocksum[b] = ws[7];
}

// phase 2: exclusive scan of 196 block sums (single tiny block)
__global__ void scan_sums() {
    int t = threadIdx.x;
    int v = (t < SCAN_BLOCKS) ? g_blocksum[t] : 0;
    int lane = t & 31, w = t >> 5;
    int incl = v;
#pragma unroll
    for (int o = 1; o < 32; o <<= 1) {
        int y = __shfl_up_sync(0xffffffffu, incl, o);
        if (lane >= o) incl += y;
    }
    __shared__ int ws[8];
    if (lane == 31) ws[w] = incl;
    __syncthreads();
    if (t < 8) {
        int x = ws[t];
#pragma unroll
        for (int o = 1; o < 8; o <<= 1) {
            int y = __shfl_up_sync(0xffu, x, o, 8);
            if (t >= o) x += y;
        }
        ws[t] = x;
    }
    __syncthreads();
    int excl = incl - v + (w > 0 ? ws[w - 1] : 0);
    if (t < SCAN_BLOCKS) g_blocksum[t] = excl;
}

// phase 3: add block offsets, init cursor
__global__ void scan_add() {
    int b = blockIdx.x, t = threadIdx.x;
    int i = b * 256 + t;
    if (i >= N_NODES) return;
    int off = g_offset[i] + g_blocksum[b];
    g_offset[i] = off;
    g_cursor[i] = off;
}

__global__ void scatter_kernel(const int* __restrict__ esrc, const int* __restrict__ edst,
                               const float* __restrict__ ew) {
    int i = blockIdx.x * blockDim.x + threadIdx.x;
    if (i >= N_EDGES) return;
    int d = edst[i];
    int pos = atomicAdd(&g_cursor[d], 1);
    g_sorted_src[pos] = esrc[i];
    g_sorted_w[pos] = ew[i];
}

__global__ void agg_kernel(const float* __restrict__ Wm, const float* __restrict__ bm) {
    int gw = (blockIdx.x * blockDim.x + threadIdx.x) >> 5;
    int lane = threadIdx.x & 31;
    if (gw >= N_NODES) return;

    int start = g_offset[gw];
    int cnt = (gw + 1 < N_NODES ? g_offset[gw + 1] : N_EDGES) - start;
    float4 outv = make_float4(0.f, 0.f, 0.f, 0.f);
    if (cnt > 0) {
        float4 w4 = *(const float4*)(Wm + 256 * 128 + lane * 4);
        float4 m = make_float4(-CUDART_INF_F, -CUDART_INF_F, -CUDART_INF_F, -CUDART_INF_F);
        int e = start, end = start + cnt;
        for (; e < end; e++) {
            int s = g_sorted_src[e];
            float w = g_sorted_w[e];
            float4 p = *(const float4*)(g_P + (size_t)s * PW + lane * 4);
            m.x = fmaxf(m.x, fmaf(w, w4.x, p.x));
            m.y = fmaxf(m.y, fmaf(w, w4.y, p.y));
            m.z = fmaxf(m.z, fmaf(w, w4.z, p.z));
            m.w = fmaxf(m.w, fmaf(w, w4.w, p.w));
        }
        float4 q = *(const float4*)(g_P + (size_t)gw * PW + 128 + lane * 4);
        float4 b = *(const float4*)(bm + lane * 4);
        outv.x = q.x + b.x + m.x;
        outv.y = q.y + b.y + m.y;
        outv.z = q.z + b.z + m.z;
        outv.w = q.w + b.w + m.w;
    }
    *(float4*)(g_agg + (size_t)gw * HID + lane * 4) = outv;
}

// ---------------- launch ----------------
extern "C" void kernel_launch(void* const* d_in, const int* in_sizes, int n_in,
                              void* d_out, int out_size) {
    const float* z    = (const float*)d_in[0];
    const float* ew   = (const float*)d_in[1];
    const int*   esrc = (const int*)d_in[2];
    const int*   edst = (const int*)d_in[3];
    const float* Wm   = (const float*)d_in[4];
    const float* bm   = (const float*)d_in[5];
    const float* W1   = (const float*)d_in[6];
    const float* b1   = (const float*)d_in[7];
    const float* W2   = (const float*)d_in[8];
    const float* b2   = (const float*)d_in[9];
    float* out = (float*)d_out;

    float *P, *AGG, *HIDN;
    cudaGetSymbolAddress((void**)&P, g_P);
    cudaGetSymbolAddress((void**)&AGG, g_agg);
    cudaGetSymbolAddress((void**)&HIDN, g_hidden);

    static bool attr_set = false;
    if (!attr_set) {
        cudaFuncSetAttribute(mma_gemm, cudaFuncAttributeMaxDynamicSharedMemorySize, SM_TOTAL);
        attr_set = true;
    }

    const int NT = (N_NODES + 127) / 128;  // 391 row tiles

    zero_count_kernel<<<SCAN_BLOCKS, 256>>>();

    // P[:,0:128)=z@Ws, [128:256)=z@Wd, [256:384)=z@W1a  (fused via grid.y)
    mma_gemm<<<dim3(NT, 3), 256, SM_TOTAL>>>(
        z, Wm + 128 * 128, Wm, W1, nullptr, nullptr, 0, P, PW, N_NODES, 0);

    hist_kernel<<<N_EDGES / 256, 256>>>(edst);
    scan_local<<<SCAN_BLOCKS, 256>>>();
    scan_sums<<<1, 256>>>();
    scan_add<<<SCAN_BLOCKS, 256>>>();
    scatter_kernel<<<N_EDGES / 256, 256>>>(esrc, edst, ew);
    agg_kernel<<<(N_NODES * 32 + 255) / 256, 256>>>(Wm, bm);

    // hidden = relu(agg @ W1b + b1 + P[:,256:384))
    mma_gemm<<<dim3(NT, 1), 256, SM_TOTAL>>>(
        AGG, W1 + 128 * 128, nullptr, nullptr, b1, P + 256, PW, HIDN, HID, N_NODES, 1);

    // out = hidden @ W2 + b2
    mma_gemm<<<dim3(NT, 1), 256, SM_TOTAL>>>(
        HIDN, W2, nullptr, nullptr, b2, nullptr, 0, out, HID, N_NODES, 0);
}